// round 17
// baseline (speedup 1.0000x reference)
#include <cuda_runtime.h>
#include <cuda_bf16.h>
#include <cstdint>

#define BB 8
#define SS 2048
#define DD 64
#define NSAMP 50
#define NTY 11

typedef unsigned long long u64;
typedef unsigned int u32;

__device__ __nv_bfloat16 g_peh[BB * SS * DD];   // pe hi plane (2 MB)
__device__ __nv_bfloat16 g_pel[BB * SS * DD];   // pe lo plane (2 MB)
__device__ __nv_bfloat16 g_wplanes[64 * 136];   // W_noise^T bf16 hi|lo (B_s layout)
__device__ __nv_bfloat16 g_winplanes[64 * 136]; // W_in^T  bf16 hi|lo (B_s layout)
__device__ float g_proj[BB * SS * DD];          // proj = hidden @ W_in^T (4 MB)
__device__ float g_gate[NTY * NTY];             // sigmoid(-|emb_a - emb_b|) LUT

// ---- misc helpers -----------------------------------------------------------
__device__ __forceinline__ float softplusf(float x) {
    return fmaxf(x, 0.0f) + log1pf(expf(-fabsf(x)));
}
__device__ __forceinline__ void cp16(void* dst, const void* src) {
    unsigned sa = (unsigned)__cvta_generic_to_shared(dst);
    asm volatile("cp.async.ca.shared.global [%0],[%1],16;" :: "r"(sa), "l"(src));
}
__device__ __forceinline__ void cp4(void* dst, const void* src) {
    unsigned sa = (unsigned)__cvta_generic_to_shared(dst);
    asm volatile("cp.async.ca.shared.global [%0],[%1],4;" :: "r"(sa), "l"(src));
}
__device__ __forceinline__ void cp_commit() { asm volatile("cp.async.commit_group;"); }
__device__ __forceinline__ void cp_wait0()  { asm volatile("cp.async.wait_group 0;"); }

// ---- HMMA helpers (sm_80+ PTX) -----------------------------------------------
__device__ __forceinline__ u32 smem_u32(const void* p) {
    return (u32)__cvta_generic_to_shared(p);
}
#define LDSM_X4(r, a) \
    asm volatile("ldmatrix.sync.aligned.m8n8.x4.shared.b16 {%0,%1,%2,%3},[%4];" \
        : "=r"((r)[0]), "=r"((r)[1]), "=r"((r)[2]), "=r"((r)[3]) : "r"(a))
#define LDSM_X4T(r, a) \
    asm volatile("ldmatrix.sync.aligned.m8n8.x4.trans.shared.b16 {%0,%1,%2,%3},[%4];" \
        : "=r"((r)[0]), "=r"((r)[1]), "=r"((r)[2]), "=r"((r)[3]) : "r"(a))
#define MMA16816(c, a0, a1, a2, a3, b0, b1) \
    asm volatile("mma.sync.aligned.m16n8k16.row.col.f32.bf16.bf16.f32 " \
        "{%0,%1,%2,%3},{%4,%5,%6,%7},{%8,%9},{%0,%1,%2,%3};" \
        : "+f"((c)[0]), "+f"((c)[1]), "+f"((c)[2]), "+f"((c)[3]) \
        : "r"(a0), "r"(a1), "r"(a2), "r"(a3), "r"(b0), "r"(b1))

// float2 -> bf16x2 hi and lo (3-term split source)
__device__ __forceinline__ void cvt_hilo(float2 f, u32& hi, u32& lo) {
    __nv_bfloat162 h2 = __floats2bfloat162_rn(f.x, f.y);
    hi = *(u32*)&h2;
    float hx = __bfloat162float(__low2bfloat16(h2));
    float hy = __bfloat162float(__high2bfloat16(h2));
    __nv_bfloat162 l2 = __floats2bfloat162_rn(f.x - hx, f.y - hy);
    lo = *(u32*)&l2;
}

// ---------------------------------------------------------------------------
// Kernel 1: pe bf16 hi/lo planes
// ---------------------------------------------------------------------------
__global__ void pe_kernel(const float* __restrict__ etime,
                          const float* __restrict__ Wt_pos) {
    int idx = blockIdx.x * blockDim.x + threadIdx.x;
    if (idx >= BB * SS * 32) return;
    int k = idx & 31;
    int s = (idx >> 5) & (SS - 1);
    int b = idx >> 16;
    int bs = b * SS + s;
    float t = etime[bs];
    float div = expf((float)(2 * k) * -0.14391156831212787f);
    float a = (float)s * div + t * Wt_pos[k];
    float sv, cv;
    __sincosf(a, &sv, &cv);
    __nv_bfloat16 sh = __float2bfloat16(sv);
    __nv_bfloat16 ch = __float2bfloat16(cv);
    g_peh[bs * DD + k]      = sh;
    g_pel[bs * DD + k]      = __float2bfloat16(sv - __bfloat162float(sh));
    g_peh[bs * DD + 32 + k] = ch;
    g_pel[bs * DD + 32 + k] = __float2bfloat16(cv - __bfloat162float(ch));
}

// ---------------------------------------------------------------------------
// Kernel 1b: W planes (ldmatrix layout) + type-pair gate LUT
// ---------------------------------------------------------------------------
__global__ void prep_w_kernel(const float* __restrict__ W_noise,
                              const float* __restrict__ W_in,
                              const float* __restrict__ type_table) {
    int idx = blockIdx.x * blockDim.x + threadIdx.x;
    if (idx < NTY * NTY) {
        int a = idx / NTY, c = idx % NTY;
        float ea = (a == 0) ? 0.0f : type_table[a] * 8.0f;
        float ec = (c == 0) ? 0.0f : type_table[c] * 8.0f;
        g_gate[idx] = 1.0f / (1.0f + expf(fabsf(ea - ec)));
    }
    if (idx >= 4096) return;
    int e = idx >> 6, d = idx & 63;
    {
        float v = W_noise[idx];
        __nv_bfloat16 hi = __float2bfloat16(v);
        g_wplanes[d * 136 + e]      = hi;
        g_wplanes[d * 136 + 64 + e] = __float2bfloat16(v - __bfloat162float(hi));
    }
    {
        float v = W_in[idx];
        __nv_bfloat16 hi = __float2bfloat16(v);
        g_winplanes[d * 136 + e]      = hi;
        g_winplanes[d * 136 + 64 + e] = __float2bfloat16(v - __bfloat162float(hi));
    }
}

// ---------------------------------------------------------------------------
// Kernel 2: hidden (HMMA) + LayerNorm + proj MMA.  256 threads.
// ---------------------------------------------------------------------------
__global__ __launch_bounds__(256) void hidden_hmma_kernel(
    const float* __restrict__ etime,
    const int*   __restrict__ etype,
    const float* __restrict__ gamma,
    const float* __restrict__ beta,
    float* __restrict__ hidden_out) {
    __shared__ __align__(16) __nv_bfloat16 A_s[64][136];
    __shared__ __align__(16) __nv_bfloat16 B_s[64][136];
    __shared__ float ti_s[64];
    __shared__ int   tyi_s[64];
    __shared__ float tj_s[2][64];
    __shared__ int   tyj_s[2][64];
    __shared__ float gm_s[64], bt_s[64];
    __shared__ float gate_s[NTY * NTY];
    __shared__ float psum_s[2][64], psq_s[2][64];

    const int b   = blockIdx.y;
    const int T   = 31 - blockIdx.x;
    const int tid = threadIdx.x;
    const int lane = tid & 31;
    const int wid  = tid >> 5;
    const int wid4 = wid & 3;
    const int whalf = wid >> 2;

    const float* etb = etime + b * SS;
    const int*   tyb = etype + b * SS;
    const __nv_bfloat16* peh = g_peh + (size_t)b * SS * DD;
    const __nv_bfloat16* pel = g_pel + (size_t)b * SS * DD;

    if (tid < 64) {
        ti_s[tid]  = etb[T * 64 + tid];
        tyi_s[tid] = tyb[T * 64 + tid];
        tj_s[0][tid]  = etb[tid];
        tyj_s[0][tid] = tyb[tid];
        gm_s[tid] = gamma[tid];
        bt_s[tid] = beta[tid];
    } else if (tid < 64 + NTY * NTY) {
        gate_s[tid - 64] = g_gate[tid - 64];
    }

    float acc[4][4];
#pragma unroll
    for (int n = 0; n < 4; n++)
#pragma unroll
        for (int i = 0; i < 4; i++) acc[n][i] = 0.0f;

    const u32 Abase = smem_u32(A_s);
    const u32 Bbase = smem_u32(B_s);
    const int arow = 16 * wid4 + (lane & 15);
    const int acol = (lane >> 4) * 8;
    const int bk = (lane & 7) + 8 * ((lane >> 3) & 1);
    const int bn = 8 * (lane >> 4);
    const int srow = tid >> 2;          // score row 0..63
    const int sjh  = (tid & 3) * 16;    // 16 evals per thread
    const int iglob = T * 64 + srow;

    __syncthreads();

    for (int jt = 0; jt <= T; jt++) {
        const int buf = jt & 1;
        const int j0 = jt * 64;
        {
#pragma unroll
            for (int r = 0; r < 4; r++) {
                const int idx = tid + 256 * r;
                const int row = idx >> 4;
                const int pl  = (idx >> 3) & 1;
                const int c   = idx & 7;
                const __nv_bfloat16* src = pl ? pel : peh;
                cp16(&B_s[row][pl * 64 + c * 8], src + (j0 + row) * DD + c * 8);
            }
            if (jt < T) {
                const int nb = buf ^ 1;
                if (tid < 64)       cp4(&tj_s[nb][tid], etb + j0 + 64 + tid);
                else if (tid < 128) cp4(&tyj_s[nb][tid - 64], tyb + j0 + 64 + tid - 64);
            }
            cp_commit();
        }
        // scores for jt; mask only exists on the diagonal tile
        {
            const float tii = ti_s[srow];
            const float* grow = &gate_s[tyi_s[srow] * NTY];
            if (jt < T) {
#pragma unroll 4
                for (int q = 0; q < 8; q++) {
                    const int jj = sjh + 2 * q;
                    const float2 tj2 = *(const float2*)&tj_s[buf][jj];
                    const float td0 = tii - tj2.x;
                    const float td1 = tii - tj2.y;
                    const float s0 = grow[tyj_s[buf][jj]]
                        * __fdividef(1.0f, 1.0f + 0.5f * td0 * td0);
                    const float s1 = grow[tyj_s[buf][jj + 1]]
                        * __fdividef(1.0f, 1.0f + 0.5f * td1 * td1);
                    u32 hi, lo;
                    cvt_hilo(make_float2(s0, s1), hi, lo);
                    *(u32*)&A_s[srow][jj]      = hi;
                    *(u32*)&A_s[srow][64 + jj] = lo;
                }
            } else {
#pragma unroll 4
                for (int q = 0; q < 8; q++) {
                    const int jj = sjh + 2 * q;
                    const float2 tj2 = *(const float2*)&tj_s[buf][jj];
                    const float td0 = tii - tj2.x;
                    const float td1 = tii - tj2.y;
                    float s0 = grow[tyj_s[buf][jj]]
                        * __fdividef(1.0f, 1.0f + 0.5f * td0 * td0);
                    float s1 = grow[tyj_s[buf][jj + 1]]
                        * __fdividef(1.0f, 1.0f + 0.5f * td1 * td1);
                    if (j0 + jj > iglob)     s0 = 0.0f;
                    if (j0 + jj + 1 > iglob) s1 = 0.0f;
                    u32 hi, lo;
                    cvt_hilo(make_float2(s0, s1), hi, lo);
                    *(u32*)&A_s[srow][jj]      = hi;
                    *(u32*)&A_s[srow][64 + jj] = lo;
                }
            }
        }
        cp_wait0();
        __syncthreads();

#pragma unroll
        for (int ks = 0; ks < 4; ks++) {
            u32 ah[4], al[4];
            LDSM_X4(ah, Abase + (u32)(arow * 272 + (ks * 16 + acol) * 2));
            LDSM_X4(al, Abase + (u32)(arow * 272 + (64 + ks * 16 + acol) * 2));
#pragma unroll
            for (int i = 0; i < 2; i++) {
                const int ntg = whalf * 2 + i;
                u32 bh[4], bl[4];
                LDSM_X4T(bh, Bbase + (u32)((ks * 16 + bk) * 272 + (ntg * 16 + bn) * 2));
                LDSM_X4T(bl, Bbase + (u32)((ks * 16 + bk) * 272 + (64 + ntg * 16 + bn) * 2));
                MMA16816(acc[2 * i],     ah[0], ah[1], ah[2], ah[3], bh[0], bh[1]);
                MMA16816(acc[2 * i + 1], ah[0], ah[1], ah[2], ah[3], bh[2], bh[3]);
                MMA16816(acc[2 * i],     ah[0], ah[1], ah[2], ah[3], bl[0], bl[1]);
                MMA16816(acc[2 * i + 1], ah[0], ah[1], ah[2], ah[3], bl[2], bl[3]);
                MMA16816(acc[2 * i],     al[0], al[1], al[2], al[3], bh[0], bh[1]);
                MMA16816(acc[2 * i + 1], al[0], al[1], al[2], al[3], bh[2], bh[3]);
            }
        }
        __syncthreads();
    }

    // prefetch W_in planes into B_s for the proj MMA
    {
#pragma unroll
        for (int r = 0; r < 5; r++) {
            const int idx = tid + 256 * r;
            if (idx < 1088) cp16((char*)B_s + idx * 16, (const char*)g_winplanes + idx * 16);
        }
        cp_commit();
    }

    // LayerNorm partials per col-half, combine via smem
#pragma unroll
    for (int h = 0; h < 2; h++) {
        const int row = 16 * wid4 + (lane >> 2) + 8 * h;
        float sum = 0.0f, sq = 0.0f;
#pragma unroll
        for (int nt = 0; nt < 4; nt++) {
#pragma unroll
            for (int j = 0; j < 2; j++) {
                const float v = acc[nt][2 * h + j];
                sum += v; sq += v * v;
            }
        }
        sum += __shfl_xor_sync(0xffffffffu, sum, 1);
        sq  += __shfl_xor_sync(0xffffffffu, sq,  1);
        sum += __shfl_xor_sync(0xffffffffu, sum, 2);
        sq  += __shfl_xor_sync(0xffffffffu, sq,  2);
        if ((lane & 3) == 0) { psum_s[whalf][row] = sum; psq_s[whalf][row] = sq; }
    }
    __syncthreads();

#pragma unroll
    for (int h = 0; h < 2; h++) {
        const int row = 16 * wid4 + (lane >> 2) + 8 * h;
        const float mu  = (psum_s[0][row] + psum_s[1][row]) * (1.0f / 64.0f);
        const float var = (psq_s[0][row] + psq_s[1][row]) * (1.0f / 64.0f) - mu * mu;
        const float inv = rsqrtf(var + 1e-6f);
        float* outp = hidden_out + ((size_t)(b * SS + T * 64 + row)) * 64;
#pragma unroll
        for (int nt = 0; nt < 4; nt++) {
            const int d0 = whalf * 32 + nt * 8 + (lane & 3) * 2;
            float2 o;
            o.x = (acc[nt][2 * h]     - mu) * inv * gm_s[d0]     + bt_s[d0];
            o.y = (acc[nt][2 * h + 1] - mu) * inv * gm_s[d0 + 1] + bt_s[d0 + 1];
            *(float2*)(outp + d0) = o;
            u32 hi, lo;
            cvt_hilo(o, hi, lo);
            *(u32*)&A_s[row][d0]      = hi;
            *(u32*)&A_s[row][64 + d0] = lo;
        }
    }
    cp_wait0();
    __syncthreads();

    // proj MMA: proj = hidden @ W_in^T
#pragma unroll
    for (int n = 0; n < 4; n++)
#pragma unroll
        for (int i = 0; i < 4; i++) acc[n][i] = 0.0f;
#pragma unroll
    for (int ks = 0; ks < 4; ks++) {
        u32 ah[4], al[4];
        LDSM_X4(ah, Abase + (u32)(arow * 272 + (ks * 16 + acol) * 2));
        LDSM_X4(al, Abase + (u32)(arow * 272 + (64 + ks * 16 + acol) * 2));
#pragma unroll
        for (int i = 0; i < 2; i++) {
            const int ntg = whalf * 2 + i;
            u32 bh[4], bl[4];
            LDSM_X4T(bh, Bbase + (u32)((ks * 16 + bk) * 272 + (ntg * 16 + bn) * 2));
            LDSM_X4T(bl, Bbase + (u32)((ks * 16 + bk) * 272 + (64 + ntg * 16 + bn) * 2));
            MMA16816(acc[2 * i],     ah[0], ah[1], ah[2], ah[3], bh[0], bh[1]);
            MMA16816(acc[2 * i + 1], ah[0], ah[1], ah[2], ah[3], bh[2], bh[3]);
            MMA16816(acc[2 * i],     ah[0], ah[1], ah[2], ah[3], bl[0], bl[1]);
            MMA16816(acc[2 * i + 1], ah[0], ah[1], ah[2], ah[3], bl[2], bl[3]);
            MMA16816(acc[2 * i],     al[0], al[1], al[2], al[3], bh[0], bh[1]);
            MMA16816(acc[2 * i + 1], al[0], al[1], al[2], al[3], bh[2], bh[3]);
        }
    }
#pragma unroll
    for (int h = 0; h < 2; h++) {
        const int row = 16 * wid4 + (lane >> 2) + 8 * h;
        float* outp = g_proj + ((size_t)(b * SS + T * 64 + row)) * 64;
#pragma unroll
        for (int nt = 0; nt < 4; nt++) {
            const int d0 = whalf * 32 + nt * 8 + (lane & 3) * 2;
            float2 o;
            o.x = acc[nt][2 * h];
            o.y = acc[nt][2 * h + 1];
            *(float2*)(outp + d0) = o;
        }
    }
}

// ---------------------------------------------------------------------------
// Kernel 3: decoder on HMMA. A-fragments loaded DIRECTLY from global noise
// (no STS/LDSM round-trip), B = W planes resident in smem. No syncs inside
// the chunk loop; per-warp partials reduced once at the end.
// ---------------------------------------------------------------------------
__global__ __launch_bounds__(128) void decoder_hmma_kernel(
    const float* __restrict__ noise,
    const float* __restrict__ W_event,
    float* __restrict__ mean_out) {
    __shared__ __align__(16) __nv_bfloat16 B_s[64][136];
    __shared__ float pj_s[8][64];
    __shared__ float wev_s[64];
    __shared__ float wpart[8][4];

    const int tid  = threadIdx.x;
    const int lane = tid & 31;
    const int wid  = tid >> 5;
    const int b  = blockIdx.x >> 8;
    const int s0 = (blockIdx.x & 255) * 8;
    const int bs0 = b * SS + s0;

    {
        const char* wsrc = (const char*)g_wplanes;
#pragma unroll
        for (int r = 0; r < 9; r++) {
            const int idx = tid + 128 * r;
            if (idx < 1088) cp16((char*)B_s + idx * 16, wsrc + idx * 16);
        }
        cp16(&pj_s[0][0] + tid * 4, g_proj + (size_t)bs0 * 64 + tid * 4);
        cp_commit();
        if (tid < 64) wev_s[tid] = W_event[tid];
    }
    cp_wait0();
    __syncthreads();

    const u32 Bbase = smem_u32(B_s);
    const int bk = (lane & 7) + 8 * ((lane >> 3) & 1);
    const int bn = 8 * (lane >> 4);
    const int gr = lane >> 2;
    const int gc = (lane & 3) * 2;
    const int r0 = 16 * wid + gr;
    const int r1 = r0 + 8;
    const int r0c = (r0 < NSAMP) ? r0 : NSAMP - 1;   // clamp pad rows (avoid OOB)
    const int r1c = (r1 < NSAMP) ? r1 : NSAMP - 1;

    for (int c = 0; c < 8; c++) {
        const float* base = noise + (size_t)(bs0 + c) * (NSAMP * 64);

        // A fragments straight from global (m16n8k16 row-major A layout)
        u32 ah[4][4], al[4][4];
#pragma unroll
        for (int ks = 0; ks < 4; ks++) {
            const int c0 = gc + 16 * ks;
            const float2 f00 = __ldg((const float2*)(base + r0c * 64 + c0));
            const float2 f01 = __ldg((const float2*)(base + r1c * 64 + c0));
            const float2 f10 = __ldg((const float2*)(base + r0c * 64 + c0 + 8));
            const float2 f11 = __ldg((const float2*)(base + r1c * 64 + c0 + 8));
            cvt_hilo(f00, ah[ks][0], al[ks][0]);
            cvt_hilo(f01, ah[ks][1], al[ks][1]);
            cvt_hilo(f10, ah[ks][2], al[ks][2]);
            cvt_hilo(f11, ah[ks][3], al[ks][3]);
        }

        float acc[8][4];
#pragma unroll
        for (int n = 0; n < 8; n++)
#pragma unroll
            for (int i = 0; i < 4; i++) acc[n][i] = 0.0f;

#pragma unroll
        for (int ks = 0; ks < 4; ks++) {
#pragma unroll
            for (int ntp = 0; ntp < 4; ntp++) {
                u32 bh[4], bl[4];
                LDSM_X4T(bh, Bbase + (u32)((ks * 16 + bk) * 272 + (ntp * 16 + bn) * 2));
                LDSM_X4T(bl, Bbase + (u32)((ks * 16 + bk) * 272 + (64 + ntp * 16 + bn) * 2));
                MMA16816(acc[2 * ntp],     ah[ks][0], ah[ks][1], ah[ks][2], ah[ks][3], bh[0], bh[1]);
                MMA16816(acc[2 * ntp + 1], ah[ks][0], ah[ks][1], ah[ks][2], ah[ks][3], bh[2], bh[3]);
                MMA16816(acc[2 * ntp],     ah[ks][0], ah[ks][1], ah[ks][2], ah[ks][3], bl[0], bl[1]);
                MMA16816(acc[2 * ntp + 1], ah[ks][0], ah[ks][1], ah[ks][2], ah[ks][3], bl[2], bl[3]);
                MMA16816(acc[2 * ntp],     al[ks][0], al[ks][1], al[ks][2], al[ks][3], bh[0], bh[1]);
                MMA16816(acc[2 * ntp + 1], al[ks][0], al[ks][1], al[ks][2], al[ks][3], bh[2], bh[3]);
            }
        }

        // epilogue: g per sample row, softplus, per-warp partial (no syncs)
        float spsum = 0.0f;
#pragma unroll
        for (int h = 0; h < 2; h++) {
            const int row = r0 + 8 * h;
            float g = 0.0f;
#pragma unroll
            for (int nt = 0; nt < 8; nt++) {
#pragma unroll
                for (int j = 0; j < 2; j++) {
                    const int e = nt * 8 + gc + j;
                    const float z = acc[nt][2 * h + j] + pj_s[c][e];
                    g = fmaf(fmaxf(z, 0.0f), wev_s[e], g);
                }
            }
            g += __shfl_xor_sync(0xffffffffu, g, 1);
            g += __shfl_xor_sync(0xffffffffu, g, 2);
            if ((lane & 3) == 0 && row < NSAMP) spsum += softplusf(g);
        }
#pragma unroll
        for (int o = 16; o > 0; o >>= 1)
            spsum += __shfl_xor_sync(0xffffffffu, spsum, o);
        if (lane == 0) wpart[c][wid] = spsum;
    }
    __syncthreads();

    if (wid == 0) {
        float v = wpart[lane >> 2][lane & 3];
        v += __shfl_xor_sync(0xffffffffu, v, 1);
        v += __shfl_xor_sync(0xffffffffu, v, 2);
        if ((lane & 3) == 0) mean_out[bs0 + (lane >> 2)] = v * (1.0f / NSAMP);
    }
}

// ---------------------------------------------------------------------------
extern "C" void kernel_launch(void* const* d_in, const int* in_sizes, int n_in,
                              void* d_out, int out_size) {
    const int*   event_type = (const int*)d_in[0];
    const float* event_time = (const float*)d_in[1];
    const float* noise      = (const float*)d_in[3];
    const float* Wt_pos     = (const float*)d_in[4];
    const float* type_table = (const float*)d_in[5];
    const float* gamma      = (const float*)d_in[6];
    const float* beta       = (const float*)d_in[7];
    const float* W_in       = (const float*)d_in[8];
    const float* W_noise    = (const float*)d_in[9];
    const float* W_event    = (const float*)d_in[10];

    float* out        = (float*)d_out;
    float* mean_out   = out;               // [B,S]
    float* hidden_out = out + BB * SS;     // [B,S,D]

    pe_kernel<<<(BB * SS * 32 + 255) / 256, 256>>>(event_time, Wt_pos);
    prep_w_kernel<<<32, 128>>>(W_noise, W_in, type_table);
    hidden_hmma_kernel<<<dim3(32, BB), 256>>>(event_time, event_type,
                                              gamma, beta, hidden_out);
    decoder_hmma_kernel<<<BB * SS / 8, 128>>>(noise, W_event, mean_out);
}